// round 4
// baseline (speedup 1.0000x reference)
#include <cuda_runtime.h>
#include <stdint.h>

// Problem constants (fixed by the reference)
#define MAXN 100000
#define MAXE 600000
#define F 128
#define BN_EPS 1e-5f

// ---------------- device scratch (no allocations allowed) ----------------
__device__ __align__(16) float g_h[(size_t)MAXN * F];     // h = x @ W
__device__ __align__(16) float g_agg[(size_t)MAXN * F];   // relu(agg) after aggregate
__device__ int   g_deg[MAXN];     // in-degree (edges only, excl. self loop)
__device__ int   g_off[MAXN];     // CSR offsets (exclusive scan of deg)
__device__ int   g_cur[MAXN];     // fill cursors
__device__ int   g_src[MAXE];     // CSR: source node per slot, grouped by dst
__device__ float g_dinv[MAXN];    // rsqrt(deg+1)
__device__ float g_sum[F];
__device__ float g_sumsq[F];
__device__ float g_scale[F];
__device__ float g_shift[F];
__device__ int   g_is64;          // edge_index dtype flag (1 = int64, 0 = int32)

// ---------------- detect edge_index dtype ----------------
// If the buffer is int64, every entry's hi-word is 0 and value < n.
// If it is int32 reinterpreted as int64, values are >= 2^32 w.h.p.
// Only reads the first 16 "row" entries -> in bounds under both layouts.
__global__ void detect_kernel(const void* ei, int n) {
    if (threadIdx.x == 0 && blockIdx.x == 0) {
        const long long* p = (const long long*)ei;
        int ok = 1;
#pragma unroll
        for (int i = 0; i < 16; i++) {
            long long v = p[i];
            if (v < 0 || v >= n) { ok = 0; break; }
        }
        g_is64 = ok;
    }
}

// ---------------- init: zero degree + stat accumulators ----------------
__global__ void init_kernel(int n) {
    int i = blockIdx.x * blockDim.x + threadIdx.x;
    if (i < n) g_deg[i] = 0;
    if (i < F) { g_sum[i] = 0.f; g_sumsq[i] = 0.f; }
}

// ---------------- degree histogram over destination (col) ----------------
__global__ void deg_kernel(const void* __restrict__ ei, int E) {
    int e = blockIdx.x * blockDim.x + threadIdx.x;
    if (e < E) {
        int c;
        if (g_is64) c = (int)((const long long*)ei)[E + e];
        else        c = ((const int*)ei)[E + e];
        atomicAdd(&g_deg[c], 1);
    }
}

// ---------------- single-block exclusive scan (warp-shuffle based) ----------
// Also produces dinv[i] = rsqrt(deg[i]+1) and initializes cursors.
__global__ void scan_kernel(int n) {
    __shared__ int wsum[32];
    __shared__ int chunk_total;
    const int t = threadIdx.x;
    const int lane = t & 31;
    const int w = t >> 5;
    int carry = 0;
    for (int base = 0; base < n; base += 1024) {
        int i = base + t;
        int d = (i < n) ? g_deg[i] : 0;
        int v = d;
#pragma unroll
        for (int o = 1; o < 32; o <<= 1) {
            int a = __shfl_up_sync(0xffffffffu, v, o);
            if (lane >= o) v += a;
        }
        if (lane == 31) wsum[w] = v;
        __syncthreads();
        if (w == 0) {
            int s = wsum[lane];
#pragma unroll
            for (int o = 1; o < 32; o <<= 1) {
                int a = __shfl_up_sync(0xffffffffu, s, o);
                if (lane >= o) s += a;
            }
            wsum[lane] = s;
            if (lane == 31) chunk_total = s;
        }
        __syncthreads();
        int wpre = (w == 0) ? 0 : wsum[w - 1];
        int excl = carry + wpre + v - d;
        if (i < n) {
            g_off[i] = excl;
            g_cur[i] = excl;
            g_dinv[i] = rsqrtf((float)(d + 1));
        }
        carry += chunk_total;
        __syncthreads();
    }
}

// ---------------- CSR fill ----------------
__global__ void fill_kernel(const void* __restrict__ ei, int E) {
    int e = blockIdx.x * blockDim.x + threadIdx.x;
    if (e < E) {
        int r, c;
        if (g_is64) {
            r = (int)((const long long*)ei)[e];
            c = (int)((const long long*)ei)[E + e];
        } else {
            r = ((const int*)ei)[e];
            c = ((const int*)ei)[E + e];
        }
        int p = atomicAdd(&g_cur[c], 1);
        g_src[p] = r;
    }
}

// ---------------- fp32 GEMM: Y[n,128] = X[n,128] @ Wm[128,128] (+bias) ----
// 48KB static shared: x-tile 64x128 (32KB) + W k-chunk 32x128 (16KB), 4 chunks.
#define GEMM_BM 64
#define GEMM_BK 32

template <bool TO_GH>
__global__ void gemm_kernel(const float* __restrict__ X,
                            const float* __restrict__ Wm,
                            const float* __restrict__ bias,
                            float* __restrict__ Yext, int n) {
    __shared__ float xs[GEMM_BM * F];   // 32 KB
    __shared__ float ws[GEMM_BK * F];   // 16 KB

    const int t = threadIdx.x;          // 256 threads
    const int block_row = blockIdx.x * GEMM_BM;

    const int rows = min(GEMM_BM, n - block_row);
    const int nf4 = rows * (F / 4);
    const float4* X4 = (const float4*)(X + (size_t)block_row * F);
    float4* xs4 = (float4*)xs;
#pragma unroll
    for (int i = t; i < GEMM_BM * (F / 4); i += 256)
        xs4[i] = (i < nf4) ? X4[i] : make_float4(0.f, 0.f, 0.f, 0.f);

    const int tx = t & 31, ty = t >> 5;
    const int c0 = tx * 4;
    const int r0 = ty * 8;

    float acc[8][4];
#pragma unroll
    for (int i = 0; i < 8; i++)
#pragma unroll
        for (int j = 0; j < 4; j++) acc[i][j] = 0.f;

    const float4* W4 = (const float4*)Wm;
    float4* ws4 = (float4*)ws;

#pragma unroll
    for (int kc = 0; kc < F / GEMM_BK; kc++) {
        __syncthreads();
#pragma unroll
        for (int i = 0; i < 4; i++)
            ws4[i * 256 + t] = W4[kc * 1024 + i * 256 + t];
        __syncthreads();

#pragma unroll 8
        for (int k = 0; k < GEMM_BK; k++) {
            float4 wv = *(const float4*)&ws[k * F + c0];
#pragma unroll
            for (int i = 0; i < 8; i++) {
                float xv = xs[(r0 + i) * F + kc * GEMM_BK + k];
                acc[i][0] = fmaf(xv, wv.x, acc[i][0]);
                acc[i][1] = fmaf(xv, wv.y, acc[i][1]);
                acc[i][2] = fmaf(xv, wv.z, acc[i][2]);
                acc[i][3] = fmaf(xv, wv.w, acc[i][3]);
            }
        }
    }

    float4 bv = make_float4(0.f, 0.f, 0.f, 0.f);
    if (bias) bv = *(const float4*)&bias[c0];
    float* Y = TO_GH ? g_h : Yext;
#pragma unroll
    for (int i = 0; i < 8; i++) {
        int r = block_row + r0 + i;
        if (r < n) {
            float4 o = make_float4(acc[i][0] + bv.x, acc[i][1] + bv.y,
                                   acc[i][2] + bv.z, acc[i][3] + bv.w);
            *(float4*)&Y[(size_t)r * F + c0] = o;
        }
    }
}

// ---------------- aggregate (gather) + self-loop + bias + ReLU + BN stats --
// one warp per destination node; 32 lanes x float4 = 128 feats
__global__ void aggregate_kernel(const float* __restrict__ b, int n) {
    __shared__ float bsum[F];
    __shared__ float bsq[F];
    const int t = threadIdx.x;
    if (t < F) { bsum[t] = 0.f; bsq[t] = 0.f; }
    __syncthreads();

    const int node = (blockIdx.x * blockDim.x + t) >> 5;
    const int lane = t & 31;

    if (node < n) {
        const float4* h4 = (const float4*)g_h;
        float dc = g_dinv[node];
        float dc2 = dc * dc;
        int j = g_off[node];
        int end = j + g_deg[node];

        float4 acc = h4[(size_t)node * 32 + lane];
        float4 bv = ((const float4*)b)[lane];
        acc.x = fmaf(acc.x, dc2, bv.x);
        acc.y = fmaf(acc.y, dc2, bv.y);
        acc.z = fmaf(acc.z, dc2, bv.z);
        acc.w = fmaf(acc.w, dc2, bv.w);

        for (; j < end; j++) {
            int r = g_src[j];
            float nrm = dc * g_dinv[r];
            float4 v = h4[(size_t)r * 32 + lane];
            acc.x = fmaf(v.x, nrm, acc.x);
            acc.y = fmaf(v.y, nrm, acc.y);
            acc.z = fmaf(v.z, nrm, acc.z);
            acc.w = fmaf(v.w, nrm, acc.w);
        }
        acc.x = fmaxf(acc.x, 0.f);
        acc.y = fmaxf(acc.y, 0.f);
        acc.z = fmaxf(acc.z, 0.f);
        acc.w = fmaxf(acc.w, 0.f);
        ((float4*)g_agg)[(size_t)node * 32 + lane] = acc;

        int f0 = lane * 4;
        atomicAdd(&bsum[f0 + 0], acc.x);
        atomicAdd(&bsum[f0 + 1], acc.y);
        atomicAdd(&bsum[f0 + 2], acc.z);
        atomicAdd(&bsum[f0 + 3], acc.w);
        atomicAdd(&bsq[f0 + 0], acc.x * acc.x);
        atomicAdd(&bsq[f0 + 1], acc.y * acc.y);
        atomicAdd(&bsq[f0 + 2], acc.z * acc.z);
        atomicAdd(&bsq[f0 + 3], acc.w * acc.w);
    }
    __syncthreads();
    if (t < F) {
        atomicAdd(&g_sum[t], bsum[t]);
        atomicAdd(&g_sumsq[t], bsq[t]);
    }
}

// ---------------- fold mean/var/gamma/beta into scale/shift ----------------
__global__ void finalize_stats_kernel(const float* __restrict__ gamma,
                                      const float* __restrict__ beta, int n) {
    int f = threadIdx.x;
    if (f < F) {
        float inv_n = 1.f / (float)n;
        float mean = g_sum[f] * inv_n;
        float var = g_sumsq[f] * inv_n - mean * mean;
        float istd = rsqrtf(var + BN_EPS);
        float sc = gamma[f] * istd;
        g_scale[f] = sc;
        g_shift[f] = beta[f] - mean * sc;
    }
}

// ---------------- final: out += r*scale + shift (out holds residual GEMM) --
__global__ void final_kernel(float* __restrict__ out, int n) {
    int tid = blockIdx.x * blockDim.x + threadIdx.x;
    if (tid >= n * (F / 4)) return;
    int s = tid & 31;
    float4 a = ((const float4*)g_agg)[tid];        // already ReLU'd
    float4 sc = ((const float4*)g_scale)[s];
    float4 sh = ((const float4*)g_shift)[s];
    float4 o = ((float4*)out)[tid];
    o.x += a.x * sc.x + sh.x;
    o.y += a.y * sc.y + sh.y;
    o.z += a.z * sc.z + sh.z;
    o.w += a.w * sc.w + sh.w;
    ((float4*)out)[tid] = o;
}

// ---------------- launch (kernel launches ONLY — graph-capture safe) -------
extern "C" void kernel_launch(void* const* d_in, const int* in_sizes, int n_in,
                              void* d_out, int out_size) {
    const float* x        = (const float*)d_in[0];
    const void*  ei       = d_in[1];
    const float* W        = (const float*)d_in[2];
    const float* b        = (const float*)d_in[3];
    const float* gamma    = (const float*)d_in[4];
    const float* beta     = (const float*)d_in[5];
    const float* W_res    = (const float*)d_in[6];
    const float* b_res    = (const float*)d_in[7];
    float* out            = (float*)d_out;

    const int n = in_sizes[0] / F;
    const int E = in_sizes[1] / 2;

    const int T = 256;
    detect_kernel<<<1, 32>>>(ei, n);
    init_kernel<<<(n + T - 1) / T, T>>>(n);
    deg_kernel<<<(E + T - 1) / T, T>>>(ei, E);
    scan_kernel<<<1, 1024>>>(n);
    fill_kernel<<<(E + T - 1) / T, T>>>(ei, E);
    // h = x @ W   (writes to g_h symbol directly)
    gemm_kernel<true><<<(n + GEMM_BM - 1) / GEMM_BM, T>>>(x, W, nullptr, nullptr, n);
    // out = x @ W_res + b_res  (residual path lands directly in d_out)
    gemm_kernel<false><<<(n + GEMM_BM - 1) / GEMM_BM, T>>>(x, W_res, b_res, out, n);
    // gather-aggregate + ReLU + stats
    {
        long long work = (long long)n * 32;
        aggregate_kernel<<<(int)((work + T - 1) / T), T>>>(b, n);
    }
    finalize_stats_kernel<<<1, F>>>(gamma, beta, n);
    {
        int work = n * (F / 4);
        final_kernel<<<(work + T - 1) / T, T>>>(out, n);
    }
}